// round 10
// baseline (speedup 1.0000x reference)
#include <cuda_runtime.h>
#include <cuda_bf16.h>
#include <math_constants.h>

#define H_OUT  135
#define W_OUT  240
#define NPIX   (H_OUT * W_OUT)   // 32400
#define EPS_A  1e-8f
#define Z_CLIP 0.01f

#define MAXF   4096
#define NW     16                // warps per block == face splits
#define FLEN_C 128               // max faces per split (clamped in host)
#define BLOCKT 512
#define NBLK   128               // A-tiles: 120 of 32r x 8c (rows 0..127)
#define NBLK_TOTAL 128 + 8       // + B-tiles: 8 of 7r x 30c (rows 128..134)

// Per-face folded coefficients, 3 x float4:
//  C0 = (gx0, gy0, k0, gx1)
//  C1 = (gy1, k1, gx2, gy2)
//  C2 = (k2,  zx,  zy,  zk)
// b_i = gx_i*px + gy_i*py + k_i ;  zp = zx*px + zy*py + zk
__device__ float4 g_c[MAXF * 3];
__device__ float4 g_bb[MAXF];   // (xmin-m, xmax+m, ymin-m, ymax+m); inverted if dead

__device__ __forceinline__ void project_v(float vx, float vy, float vz,
                                          float& xn, float& yn) {
    float xs = 1000.0f * (-vx) / vz + 960.0f;
    float ys = 1000.0f * vy    / vz + 540.0f;
    xn = -(2.0f * xs - 1920.0f) / 1080.0f;
    yn = -(2.0f * ys - 1080.0f) / 1080.0f;
}

__device__ __forceinline__ float pix_x(int c) {
    return -(2.0f * (float)c + 1.0f - (float)W_OUT) / 135.0f;
}
__device__ __forceinline__ float pix_y(int r_out) {
    int h = H_OUT - 1 - r_out;   // undo the [::-1] row flip
    return -(2.0f * (float)h + 1.0f - (float)H_OUT) / 135.0f;
}

// a*b - c*d with two-prod compensation (~0.5 ulp)
__device__ __forceinline__ float cross_acc(float a, float b, float c, float d) {
    float p1 = a * b;
    float e1 = fmaf(a, b, -p1);
    float p2 = c * d;
    float e2 = fmaf(c, d, -p2);
    return (p1 - p2) + (e1 - e2);
}

// a0*b0 + a1*b1 + a2*b2 with two-prod + two-sum compensation
__device__ __forceinline__ float dot3_acc(float a0, float b0,
                                          float a1, float b1,
                                          float a2, float b2) {
    float p0 = a0 * b0, e0 = fmaf(a0, b0, -p0);
    float p1 = a1 * b1, e1 = fmaf(a1, b1, -p1);
    float p2 = a2 * b2, e2 = fmaf(a2, b2, -p2);
    float s1 = p0 + p1;
    float v1 = s1 - p0;
    float t1 = (p0 - (s1 - v1)) + (p1 - v1);
    float s2 = s1 + p2;
    float v2 = s2 - s1;
    float t2 = (s1 - (s2 - v2)) + (p2 - v2);
    return s2 + (t1 + t2 + e0 + e1 + e2);
}

__global__ __launch_bounds__(128)
void face_setup_kernel(const float* __restrict__ verts,
                       const int*   __restrict__ faces,
                       int F) {
    int f = blockIdx.x * 128 + threadIdx.x;
    if (f >= F) return;

    int i0 = faces[3 * f + 0];
    int i1 = faces[3 * f + 1];
    int i2 = faces[3 * f + 2];

    float v0z = verts[3 * i0 + 2];
    float v1z = verts[3 * i1 + 2];
    float v2z = verts[3 * i2 + 2];

    float x0, y0, x1, y1, x2, y2;
    project_v(verts[3 * i0], verts[3 * i0 + 1], v0z, x0, y0);
    project_v(verts[3 * i1], verts[3 * i1 + 1], v1z, x1, y1);
    project_v(verts[3 * i2], verts[3 * i2 + 1], v2z, x2, y2);

    float area = (x1 - x0) * (y2 - y0) - (y1 - y0) * (x2 - x0);
    bool ok = (fabsf(area) > EPS_A) &&
              (v0z > Z_CLIP) && (v1z > Z_CLIP) && (v2z > Z_CLIP);

    if (!ok) {
        g_c[f * 3 + 0] = make_float4(0.0f, 0.0f, -1.0f, 0.0f);
        g_c[f * 3 + 1] = make_float4(0.0f, 0.0f, 0.0f, 0.0f);
        g_c[f * 3 + 2] = make_float4(0.0f, 0.0f, 0.0f, 0.0f);
        g_bb[f] = make_float4(CUDART_INF_F, -CUDART_INF_F,
                              CUDART_INF_F, -CUDART_INF_F);   // never passes cull
        return;
    }

    float inv = 1.0f / area;          // fp32 reciprocal, same as reference
    float dy21 = y2 - y1, dx21 = x2 - x1;
    float dy02 = y0 - y2, dx02 = x0 - x2;
    float dy10 = y1 - y0, dx10 = x1 - x0;

    float gx0 = -dy21 * inv;
    float gy0 =  dx21 * inv;
    float k0  = cross_acc(dy21, x1, dx21, y1) * inv;
    float gx1 = -dy02 * inv;
    float gy1 =  dx02 * inv;
    float k1  = cross_acc(dy02, x2, dx02, y2) * inv;
    float gx2 = -dy10 * inv;
    float gy2 =  dx10 * inv;
    float k2  = cross_acc(dy10, x0, dx10, y0) * inv;

    float zx = dot3_acc(gx0, v0z, gx1, v1z, gx2, v2z);
    float zy = dot3_acc(gy0, v0z, gy1, v1z, gy2, v2z);
    float zk = dot3_acc(k0,  v0z, k1,  v1z, k2,  v2z);

    g_c[f * 3 + 0] = make_float4(gx0, gy0, k0, gx1);
    g_c[f * 3 + 1] = make_float4(gy1, k1, gx2, gy2);
    g_c[f * 3 + 2] = make_float4(k2, zx, zy, zk);

    float m = 2e-6f;
    g_bb[f] = make_float4(fminf(x0, fminf(x1, x2)) - m,
                          fmaxf(x0, fmaxf(x1, x2)) + m,
                          fminf(y0, fminf(y1, y2)) - m,
                          fmaxf(y0, fmaxf(y1, y2)) + m);
}

__global__ __launch_bounds__(BLOCKT, 2)
void raster_tile_kernel(float* __restrict__ out, int F, int flen) {
    __shared__ float2 zf[8 * NW * 32];     // candidates [k][split][lane], 32 KB
    __shared__ int    sl[NW][FLEN_C];      // per-split cull lists, 8 KB

    int w    = threadIdx.x >> 5;
    int lane = threadIdx.x & 31;
    int b    = blockIdx.x;
    bool cfgA = (b < 120);

    int r0, c0;
    float pyl, pyh, pxl, pxh;
    if (cfgA) {                      // 32 rows (lane) x 8 cols (k)
        int band = b / 30, tc = b - band * 30;
        r0 = band * 32;  c0 = tc * 8;
        pyl = pix_y(r0);      pyh = pix_y(r0 + 31);
        pxh = pix_x(c0);      pxl = pix_x(c0 + 7);
    } else {                         // 7 rows (k) x 30 cols (lane)
        r0 = 128;  c0 = (b - 120) * 30;
        pyl = pix_y(128);     pyh = pix_y(134);
        pxh = pix_x(c0);      pxl = pix_x(c0 + 29);
    }

    // ---- cull: warp w owns faces [w*flen, w*flen + n) ----
    int fbeg = w * flen;
    int n = F - fbeg;
    if (n > flen) n = flen;
    if (n < 0) n = 0;

    // prefetch all bbox loads (MLP 4), then 4 ballot rounds
    float4 bbv[4];
    #pragma unroll
    for (int r = 0; r < 4; r++) {
        int f = r * 32 + lane;
        bbv[r] = (f < n) ? __ldg(&g_bb[fbeg + f])
                         : make_float4(CUDART_INF_F, -CUDART_INF_F,
                                       CUDART_INF_F, -CUDART_INF_F);
    }
    int* slw = sl[w];
    int nlist = 0;
    #pragma unroll
    for (int r = 0; r < 4; r++) {
        int f = r * 32 + lane;
        bool pass = (f < n) &&
                    (bbv[r].y >= pxl) && (bbv[r].x <= pxh) &&
                    (bbv[r].w >= pyl) && (bbv[r].z <= pyh);
        unsigned m = __ballot_sync(0xffffffffu, pass);
        if (pass) slw[nlist + __popc(m & ((1u << lane) - 1u))] = f;
        nlist += __popc(m);
    }

    // ---- raster this split over the tile (coeffs from L2, 1-deep prefetch) ----
    float zr[8];
    int   fr[8];
    #pragma unroll
    for (int k = 0; k < 8; k++) { zr[k] = CUDART_INF_F; fr[k] = -1; }

    if (nlist > 0) {
        int f = fbeg + slw[0];
        float4 A = __ldg(&g_c[f * 3 + 0]);
        float4 B = __ldg(&g_c[f * 3 + 1]);
        float4 C = __ldg(&g_c[f * 3 + 2]);

        if (cfgA) {
            float py = pix_y(r0 + lane);
            float px[8];
            #pragma unroll
            for (int k = 0; k < 8; k++) px[k] = pix_x(c0 + k);

            for (int j = 0; j < nlist; j++) {
                int fn = 0; float4 An, Bn, Cn;
                if (j + 1 < nlist) {
                    fn = fbeg + slw[j + 1];
                    An = __ldg(&g_c[fn * 3 + 0]);
                    Bn = __ldg(&g_c[fn * 3 + 1]);
                    Cn = __ldg(&g_c[fn * 3 + 2]);
                }

                float t0 = fmaf(A.y, py, A.z);   // gy0*py + k0
                float t1 = fmaf(B.x, py, B.y);   // gy1*py + k1
                float t2 = fmaf(B.w, py, C.x);   // gy2*py + k2
                float tz = fmaf(C.z, py, C.w);   // zy*py + zk

                #pragma unroll
                for (int k = 0; k < 8; k++) {
                    float b0 = fmaf(A.x, px[k], t0);
                    float b1 = fmaf(A.w, px[k], t1);
                    float b2 = fmaf(B.z, px[k], t2);
                    float zp = fmaf(C.y, px[k], tz);
                    float mm = fminf(fminf(b0, b1), b2);
                    float zc = (mm >= 0.0f) ? zp : CUDART_INF_F;
                    if (zc < zr[k]) { zr[k] = zc; fr[k] = f; }
                }
                f = fn; A = An; B = Bn; C = Cn;
            }
        } else {
            int cl = (lane < 30) ? lane : 29;    // lanes 30,31: garbage, never stored
            float px = pix_x(c0 + cl);
            float py[7];
            #pragma unroll
            for (int k = 0; k < 7; k++) py[k] = pix_y(128 + k);

            for (int j = 0; j < nlist; j++) {
                int fn = 0; float4 An, Bn, Cn;
                if (j + 1 < nlist) {
                    fn = fbeg + slw[j + 1];
                    An = __ldg(&g_c[fn * 3 + 0]);
                    Bn = __ldg(&g_c[fn * 3 + 1]);
                    Cn = __ldg(&g_c[fn * 3 + 2]);
                }

                float u0 = fmaf(A.x, px, A.z);   // gx0*px + k0
                float u1 = fmaf(A.w, px, B.y);   // gx1*px + k1
                float u2 = fmaf(B.z, px, C.x);   // gx2*px + k2
                float uz = fmaf(C.y, px, C.w);   // zx*px + zk

                #pragma unroll
                for (int k = 0; k < 7; k++) {
                    float b0 = fmaf(A.y, py[k], u0);
                    float b1 = fmaf(B.x, py[k], u1);
                    float b2 = fmaf(B.w, py[k], u2);
                    float zp = fmaf(C.z, py[k], uz);
                    float mm = fminf(fminf(b0, b1), b2);
                    float zc = (mm >= 0.0f) ? zp : CUDART_INF_F;
                    if (zc < zr[k]) { zr[k] = zc; fr[k] = f; }
                }
                f = fn; A = An; B = Bn; C = Cn;
            }
        }
    }

    // publish candidates: zf[k][w][lane] (lane-contiguous -> conflict-free)
    #pragma unroll
    for (int k = 0; k < 8; k++)
        zf[(k * NW + w) * 32 + lane] = make_float2(zr[k], __int_as_float(fr[k]));
    __syncthreads();

    // ---- per-pixel reduction over the 16 splits + direct output ----
    int t = threadIdx.x;
    if (t < 256) {
        int lane_ = t & 31;
        int k_    = t >> 5;
        bool valid;
        int row, col;
        if (cfgA) { valid = true;                       row = r0 + lane_; col = c0 + k_; }
        else      { valid = (k_ < 7) && (lane_ < 30);   row = 128 + k_;   col = c0 + lane_; }

        if (valid) {
            float zb = CUDART_INF_F;
            int   fv = -1;
            // ascending split order + strict '<'  ==  lowest-index tie-break
            #pragma unroll
            for (int ww = 0; ww < NW; ww++) {
                float2 v = zf[(k_ * NW + ww) * 32 + lane_];
                if (v.x < zb) { zb = v.x; fv = __float_as_int(v.y); }
            }

            float bb0 = -1.0f, bb1 = -1.0f, bb2 = -1.0f;
            if (fv >= 0) {
                float4 A = __ldg(&g_c[fv * 3 + 0]);
                float4 B = __ldg(&g_c[fv * 3 + 1]);
                float k2 = __ldg(&g_c[fv * 3 + 2]).x;
                float px_ = pix_x(col);
                float py_ = pix_y(row);
                if (cfgA) {   // identical op order to cfgA raster loop
                    bb0 = fmaf(A.x, px_, fmaf(A.y, py_, A.z));
                    bb1 = fmaf(A.w, px_, fmaf(B.x, py_, B.y));
                    bb2 = fmaf(B.z, px_, fmaf(B.w, py_, k2));
                } else {      // identical op order to cfgB raster loop
                    bb0 = fmaf(A.y, py_, fmaf(A.x, px_, A.z));
                    bb1 = fmaf(B.x, py_, fmaf(A.w, px_, B.y));
                    bb2 = fmaf(B.w, py_, fmaf(B.z, px_, k2));
                }
            }

            int p = row * W_OUT + col;
            out[p] = (float)fv;
            float* bary = out + NPIX + 3 * p;
            bary[0] = bb0;
            bary[1] = bb1;
            bary[2] = bb2;
        }
    }
}

extern "C" void kernel_launch(void* const* d_in, const int* in_sizes, int n_in,
                              void* d_out, int out_size) {
    const float* verts = (const float*)d_in[0];
    const int*   faces = (const int*)d_in[1];
    int F = in_sizes[1] / 3;
    if (F > MAXF) F = MAXF;

    int flen = (F + NW - 1) / NW;
    if (flen < 1) flen = 1;
    if (flen > FLEN_C) flen = FLEN_C;   // faces beyond NW*FLEN_C would be dropped;
                                        // F<=2048 here so flen=128 covers all

    face_setup_kernel<<<(F + 127) / 128, 128>>>(verts, faces, F);
    raster_tile_kernel<<<NBLK_TOTAL, BLOCKT>>>((float*)d_out, F, flen);
}

// round 11
// speedup vs baseline: 1.1151x; 1.1151x over previous
#include <cuda_runtime.h>
#include <cuda_bf16.h>
#include <math_constants.h>

#define H_OUT  135
#define W_OUT  240
#define NPIX   (H_OUT * W_OUT)   // 32400
#define EPS_A  1e-8f
#define Z_CLIP 0.01f

#define MAXF   2048
#define NW     16                // warps per block == face splits
#define FLEN_C 128               // max faces per split
#define BLOCKT 512
#define NBLK   128               // 120 A-tiles (32r x 8c, rows 0..127) + 8 B-tiles (7r x 30c)

// Per-face folded coefficients, 3 x float4:
//  C0 = (gx0, gy0, k0, gx1)
//  C1 = (gy1, k1, gx2, gy2)
//  C2 = (k2,  zx,  zy,  zk)
// b_i = gx_i*px + gy_i*py + k_i ;  zp = zx*px + zy*py + zk
__device__ float4 g_c[MAXF * 3];
__device__ float4 g_bb[MAXF];   // (xmin-m, xmax+m, ymin-m, ymax+m); inverted if dead

// K2 dynamic smem layout:
//  scc : float4[MAXF*3]      staged coeffs      = 98304 B
//  zf  : float2[8*NW*32]     candidates         = 32768 B
//  sl  : int[NW][FLEN_C]     cull lists         =  8192 B
#define SCC_OFF 0
#define ZF_OFF  (MAXF * 3 * 16)
#define SL_OFF  (ZF_OFF + 8 * NW * 32 * 8)
#define SMEM_K2 (SL_OFF + NW * FLEN_C * 4)    // 139264

__device__ __forceinline__ void project_v(float vx, float vy, float vz,
                                          float& xn, float& yn) {
    float xs = 1000.0f * (-vx) / vz + 960.0f;
    float ys = 1000.0f * vy    / vz + 540.0f;
    xn = -(2.0f * xs - 1920.0f) / 1080.0f;
    yn = -(2.0f * ys - 1080.0f) / 1080.0f;
}

__device__ __forceinline__ float pix_x(int c) {
    return -(2.0f * (float)c + 1.0f - (float)W_OUT) / 135.0f;
}
__device__ __forceinline__ float pix_y(int r_out) {
    int h = H_OUT - 1 - r_out;   // undo the [::-1] row flip
    return -(2.0f * (float)h + 1.0f - (float)H_OUT) / 135.0f;
}

// a*b - c*d with two-prod compensation (~0.5 ulp)
__device__ __forceinline__ float cross_acc(float a, float b, float c, float d) {
    float p1 = a * b;
    float e1 = fmaf(a, b, -p1);
    float p2 = c * d;
    float e2 = fmaf(c, d, -p2);
    return (p1 - p2) + (e1 - e2);
}

// a0*b0 + a1*b1 + a2*b2 with two-prod + two-sum compensation
__device__ __forceinline__ float dot3_acc(float a0, float b0,
                                          float a1, float b1,
                                          float a2, float b2) {
    float p0 = a0 * b0, e0 = fmaf(a0, b0, -p0);
    float p1 = a1 * b1, e1 = fmaf(a1, b1, -p1);
    float p2 = a2 * b2, e2 = fmaf(a2, b2, -p2);
    float s1 = p0 + p1;
    float v1 = s1 - p0;
    float t1 = (p0 - (s1 - v1)) + (p1 - v1);
    float s2 = s1 + p2;
    float v2 = s2 - s1;
    float t2 = (s1 - (s2 - v2)) + (p2 - v2);
    return s2 + (t1 + t2 + e0 + e1 + e2);
}

__global__ __launch_bounds__(128)
void face_setup_kernel(const float* __restrict__ verts,
                       const int*   __restrict__ faces,
                       int F) {
    int f = blockIdx.x * 128 + threadIdx.x;
    if (f >= F) return;

    int i0 = faces[3 * f + 0];
    int i1 = faces[3 * f + 1];
    int i2 = faces[3 * f + 2];

    float v0z = verts[3 * i0 + 2];
    float v1z = verts[3 * i1 + 2];
    float v2z = verts[3 * i2 + 2];

    float x0, y0, x1, y1, x2, y2;
    project_v(verts[3 * i0], verts[3 * i0 + 1], v0z, x0, y0);
    project_v(verts[3 * i1], verts[3 * i1 + 1], v1z, x1, y1);
    project_v(verts[3 * i2], verts[3 * i2 + 1], v2z, x2, y2);

    float area = (x1 - x0) * (y2 - y0) - (y1 - y0) * (x2 - x0);
    bool ok = (fabsf(area) > EPS_A) &&
              (v0z > Z_CLIP) && (v1z > Z_CLIP) && (v2z > Z_CLIP);

    if (!ok) {
        g_c[f * 3 + 0] = make_float4(0.0f, 0.0f, -1.0f, 0.0f);
        g_c[f * 3 + 1] = make_float4(0.0f, 0.0f, 0.0f, 0.0f);
        g_c[f * 3 + 2] = make_float4(0.0f, 0.0f, 0.0f, 0.0f);
        g_bb[f] = make_float4(CUDART_INF_F, -CUDART_INF_F,
                              CUDART_INF_F, -CUDART_INF_F);   // never passes cull
        return;
    }

    float inv = 1.0f / area;          // fp32 reciprocal, same as reference
    float dy21 = y2 - y1, dx21 = x2 - x1;
    float dy02 = y0 - y2, dx02 = x0 - x2;
    float dy10 = y1 - y0, dx10 = x1 - x0;

    float gx0 = -dy21 * inv;
    float gy0 =  dx21 * inv;
    float k0  = cross_acc(dy21, x1, dx21, y1) * inv;
    float gx1 = -dy02 * inv;
    float gy1 =  dx02 * inv;
    float k1  = cross_acc(dy02, x2, dx02, y2) * inv;
    float gx2 = -dy10 * inv;
    float gy2 =  dx10 * inv;
    float k2  = cross_acc(dy10, x0, dx10, y0) * inv;

    float zx = dot3_acc(gx0, v0z, gx1, v1z, gx2, v2z);
    float zy = dot3_acc(gy0, v0z, gy1, v1z, gy2, v2z);
    float zk = dot3_acc(k0,  v0z, k1,  v1z, k2,  v2z);

    g_c[f * 3 + 0] = make_float4(gx0, gy0, k0, gx1);
    g_c[f * 3 + 1] = make_float4(gy1, k1, gx2, gy2);
    g_c[f * 3 + 2] = make_float4(k2, zx, zy, zk);

    float m = 2e-6f;
    g_bb[f] = make_float4(fminf(x0, fminf(x1, x2)) - m,
                          fmaxf(x0, fmaxf(x1, x2)) + m,
                          fminf(y0, fminf(y1, y2)) - m,
                          fmaxf(y0, fmaxf(y1, y2)) + m);
}

__global__ __launch_bounds__(BLOCKT)
void raster_tile_kernel(float* __restrict__ out, int F, int flen) {
    extern __shared__ char smem[];
    float4* scc = (float4*)(smem + SCC_OFF);
    float2* zf  = (float2*)(smem + ZF_OFF);
    int*    sl  = (int*)   (smem + SL_OFF);

    int w    = threadIdx.x >> 5;
    int lane = threadIdx.x & 31;
    int b    = blockIdx.x;
    bool cfgA = (b < 120);

    // ---- bulk-stage all face coefficients into shared (pipelined, MLP-rich) ----
    {
        int n3 = F * 3;
        #pragma unroll 4
        for (int j = threadIdx.x; j < n3; j += BLOCKT)
            scc[j] = __ldg(&g_c[j]);
    }

    int r0, c0;
    float pyl, pyh, pxl, pxh;
    if (cfgA) {                      // 32 rows (lane) x 8 cols (k)
        int band = b / 30, tc = b - band * 30;
        r0 = band * 32;  c0 = tc * 8;
        pyl = pix_y(r0);      pyh = pix_y(r0 + 31);
        pxh = pix_x(c0);      pxl = pix_x(c0 + 7);
    } else {                         // 7 rows (k) x 30 cols (lane)
        r0 = 128;  c0 = (b - 120) * 30;
        pyl = pix_y(128);     pyh = pix_y(134);
        pxh = pix_x(c0);      pxl = pix_x(c0 + 29);
    }

    // ---- cull (reads g_bb from global; overlaps the staging latency) ----
    int fbeg = w * flen;
    int n = F - fbeg;
    if (n > flen) n = flen;
    if (n < 0) n = 0;

    float4 bbv[4];
    #pragma unroll
    for (int r = 0; r < 4; r++) {
        int f = r * 32 + lane;
        bbv[r] = (f < n) ? __ldg(&g_bb[fbeg + f])
                         : make_float4(CUDART_INF_F, -CUDART_INF_F,
                                       CUDART_INF_F, -CUDART_INF_F);
    }
    int* slw = sl + w * FLEN_C;
    int nlist = 0;
    #pragma unroll
    for (int r = 0; r < 4; r++) {
        int f = r * 32 + lane;
        bool pass = (f < n) &&
                    (bbv[r].y >= pxl) && (bbv[r].x <= pxh) &&
                    (bbv[r].w >= pyl) && (bbv[r].z <= pyh);
        unsigned m = __ballot_sync(0xffffffffu, pass);
        if (pass) slw[nlist + __popc(m & ((1u << lane) - 1u))] = f;
        nlist += __popc(m);
    }

    __syncthreads();   // staged coeffs visible to all warps

    // ---- raster this split over the tile (coeffs from SMEM) ----
    float zr[8];
    int   fr[8];
    #pragma unroll
    for (int k = 0; k < 8; k++) { zr[k] = CUDART_INF_F; fr[k] = -1; }

    if (cfgA) {
        float py = pix_y(r0 + lane);
        float px[8];
        #pragma unroll
        for (int k = 0; k < 8; k++) px[k] = pix_x(c0 + k);

        for (int j = 0; j < nlist; j++) {
            int f = fbeg + slw[j];
            float4 A = scc[f * 3 + 0];
            float4 B = scc[f * 3 + 1];
            float4 C = scc[f * 3 + 2];

            float t0 = fmaf(A.y, py, A.z);   // gy0*py + k0
            float t1 = fmaf(B.x, py, B.y);   // gy1*py + k1
            float t2 = fmaf(B.w, py, C.x);   // gy2*py + k2
            float tz = fmaf(C.z, py, C.w);   // zy*py + zk

            #pragma unroll
            for (int k = 0; k < 8; k++) {
                float b0 = fmaf(A.x, px[k], t0);
                float b1 = fmaf(A.w, px[k], t1);
                float b2 = fmaf(B.z, px[k], t2);
                float zp = fmaf(C.y, px[k], tz);
                float mm = fminf(fminf(b0, b1), b2);
                float zc = (mm >= 0.0f) ? zp : CUDART_INF_F;
                if (zc < zr[k]) { zr[k] = zc; fr[k] = f; }
            }
        }
    } else {
        int cl = (lane < 30) ? lane : 29;    // lanes 30,31: garbage, never stored
        float px = pix_x(c0 + cl);
        float py[7];
        #pragma unroll
        for (int k = 0; k < 7; k++) py[k] = pix_y(128 + k);

        for (int j = 0; j < nlist; j++) {
            int f = fbeg + slw[j];
            float4 A = scc[f * 3 + 0];
            float4 B = scc[f * 3 + 1];
            float4 C = scc[f * 3 + 2];

            float u0 = fmaf(A.x, px, A.z);   // gx0*px + k0
            float u1 = fmaf(A.w, px, B.y);   // gx1*px + k1
            float u2 = fmaf(B.z, px, C.x);   // gx2*px + k2
            float uz = fmaf(C.y, px, C.w);   // zx*px + zk

            #pragma unroll
            for (int k = 0; k < 7; k++) {
                float b0 = fmaf(A.y, py[k], u0);
                float b1 = fmaf(B.x, py[k], u1);
                float b2 = fmaf(B.w, py[k], u2);
                float zp = fmaf(C.z, py[k], uz);
                float mm = fminf(fminf(b0, b1), b2);
                float zc = (mm >= 0.0f) ? zp : CUDART_INF_F;
                if (zc < zr[k]) { zr[k] = zc; fr[k] = f; }
            }
        }
    }

    // publish candidates: zf[k][w][lane] (lane-contiguous -> conflict-free)
    #pragma unroll
    for (int k = 0; k < 8; k++)
        zf[(k * NW + w) * 32 + lane] = make_float2(zr[k], __int_as_float(fr[k]));
    __syncthreads();

    // ---- per-pixel reduction over the 16 splits + direct output ----
    int t = threadIdx.x;
    if (t < 256) {
        int lane_ = t & 31;
        int k_    = t >> 5;
        bool valid;
        int row, col;
        if (cfgA) { valid = true;                       row = r0 + lane_; col = c0 + k_; }
        else      { valid = (k_ < 7) && (lane_ < 30);   row = 128 + k_;   col = c0 + lane_; }

        if (valid) {
            float zb = CUDART_INF_F;
            int   fv = -1;
            // ascending split order + strict '<'  ==  lowest-index tie-break
            #pragma unroll
            for (int ww = 0; ww < NW; ww++) {
                float2 v = zf[(k_ * NW + ww) * 32 + lane_];
                if (v.x < zb) { zb = v.x; fv = __float_as_int(v.y); }
            }

            float bb0 = -1.0f, bb1 = -1.0f, bb2 = -1.0f;
            if (fv >= 0) {
                float4 A = scc[fv * 3 + 0];
                float4 B = scc[fv * 3 + 1];
                float k2 = scc[fv * 3 + 2].x;
                float px_ = pix_x(col);
                float py_ = pix_y(row);
                if (cfgA) {   // identical op order to cfgA raster loop
                    bb0 = fmaf(A.x, px_, fmaf(A.y, py_, A.z));
                    bb1 = fmaf(A.w, px_, fmaf(B.x, py_, B.y));
                    bb2 = fmaf(B.z, px_, fmaf(B.w, py_, k2));
                } else {      // identical op order to cfgB raster loop
                    bb0 = fmaf(A.y, py_, fmaf(A.x, px_, A.z));
                    bb1 = fmaf(B.x, py_, fmaf(A.w, px_, B.y));
                    bb2 = fmaf(B.w, py_, fmaf(B.z, px_, k2));
                }
            }

            int p = row * W_OUT + col;
            out[p] = (float)fv;
            float* bary = out + NPIX + 3 * p;
            bary[0] = bb0;
            bary[1] = bb1;
            bary[2] = bb2;
        }
    }
}

extern "C" void kernel_launch(void* const* d_in, const int* in_sizes, int n_in,
                              void* d_out, int out_size) {
    const float* verts = (const float*)d_in[0];
    const int*   faces = (const int*)d_in[1];
    int F = in_sizes[1] / 3;
    if (F > MAXF) F = MAXF;

    int flen = (F + NW - 1) / NW;
    if (flen < 1) flen = 1;
    if (flen > FLEN_C) flen = FLEN_C;   // F <= 2048 here so all faces covered

    face_setup_kernel<<<(F + 127) / 128, 128>>>(verts, faces, F);

    cudaFuncSetAttribute(raster_tile_kernel,
                         cudaFuncAttributeMaxDynamicSharedMemorySize, SMEM_K2);
    raster_tile_kernel<<<NBLK, BLOCKT, SMEM_K2>>>((float*)d_out, F, flen);
}

// round 12
// speedup vs baseline: 1.3795x; 1.2370x over previous
#include <cuda_runtime.h>
#include <cuda_bf16.h>
#include <math_constants.h>

#define H_OUT  135
#define W_OUT  240
#define NPIX   (H_OUT * W_OUT)   // 32400
#define EPS_A  1e-8f
#define Z_CLIP 0.01f

#define MAXF   4096
#define FLEN   128               // faces per split

// Warp tile: 32 rows (lane) x 8 cols (k)
#define TROWS 32
#define TCOLS 8
#define NTR   ((H_OUT + TROWS - 1) / TROWS)   // 5
#define NTC   (W_OUT / TCOLS)                 // 30
#define NTILES (NTR * NTC)                    // 150
#define WPB   4
#define NBLKX ((NTILES + WPB - 1) / WPB)      // 38
#define BLOCK (32 * WPB)                      // 128

// Per-face folded coefficients, 3 x float4:
//  C0 = (gx0, gy0, k0, gx1)
//  C1 = (gy1, k1, gx2, gy2)
//  C2 = (k2,  zx,  zy,  zk)
// b_i = gx_i*px + gy_i*py + k_i ;  zp = zx*px + zy*py + zk
__device__ float4 g_c[MAXF * 3];
__device__ float4 g_bb[MAXF];   // (xmin-m, xmax+m, ymin-m, ymax+m); inverted if dead
// packed ((0xFFFFFFFF - z_bits) << 32) | (0xFFFFFFFF - face); 0 == empty.
// Zero-initialized at module load; tail phase resets to 0 every call.
__device__ unsigned long long g_pk[NPIX];
// arrival ticket + tail-completion counter; reset by the last tail block.
__device__ unsigned g_ctr  = 0;
__device__ unsigned g_ctr2 = 0;

__device__ __forceinline__ void project_v(float vx, float vy, float vz,
                                          float& xn, float& yn) {
    float xs = 1000.0f * (-vx) / vz + 960.0f;
    float ys = 1000.0f * vy    / vz + 540.0f;
    xn = -(2.0f * xs - 1920.0f) / 1080.0f;
    yn = -(2.0f * ys - 1080.0f) / 1080.0f;
}

__device__ __forceinline__ float pix_x(int c) {
    return -(2.0f * (float)c + 1.0f - (float)W_OUT) / 135.0f;
}
__device__ __forceinline__ float pix_y(int r_out) {
    int h = H_OUT - 1 - r_out;   // undo the [::-1] row flip
    return -(2.0f * (float)h + 1.0f - (float)H_OUT) / 135.0f;
}

// a*b - c*d with two-prod compensation (~0.5 ulp)
__device__ __forceinline__ float cross_acc(float a, float b, float c, float d) {
    float p1 = a * b;
    float e1 = fmaf(a, b, -p1);
    float p2 = c * d;
    float e2 = fmaf(c, d, -p2);
    return (p1 - p2) + (e1 - e2);
}

// a0*b0 + a1*b1 + a2*b2 with two-prod + two-sum compensation
__device__ __forceinline__ float dot3_acc(float a0, float b0,
                                          float a1, float b1,
                                          float a2, float b2) {
    float p0 = a0 * b0, e0 = fmaf(a0, b0, -p0);
    float p1 = a1 * b1, e1 = fmaf(a1, b1, -p1);
    float p2 = a2 * b2, e2 = fmaf(a2, b2, -p2);
    float s1 = p0 + p1;
    float v1 = s1 - p0;
    float t1 = (p0 - (s1 - v1)) + (p1 - v1);
    float s2 = s1 + p2;
    float v2 = s2 - s1;
    float t2 = (s1 - (s2 - v2)) + (p2 - v2);
    return s2 + (t1 + t2 + e0 + e1 + e2);
}

__global__ __launch_bounds__(128)
void face_setup_kernel(const float* __restrict__ verts,
                       const int*   __restrict__ faces,
                       int F) {
    int f = blockIdx.x * 128 + threadIdx.x;
    if (f >= F) return;

    int i0 = faces[3 * f + 0];
    int i1 = faces[3 * f + 1];
    int i2 = faces[3 * f + 2];

    float v0z = verts[3 * i0 + 2];
    float v1z = verts[3 * i1 + 2];
    float v2z = verts[3 * i2 + 2];

    float x0, y0, x1, y1, x2, y2;
    project_v(verts[3 * i0], verts[3 * i0 + 1], v0z, x0, y0);
    project_v(verts[3 * i1], verts[3 * i1 + 1], v1z, x1, y1);
    project_v(verts[3 * i2], verts[3 * i2 + 1], v2z, x2, y2);

    float area = (x1 - x0) * (y2 - y0) - (y1 - y0) * (x2 - x0);
    bool ok = (fabsf(area) > EPS_A) &&
              (v0z > Z_CLIP) && (v1z > Z_CLIP) && (v2z > Z_CLIP);

    if (!ok) {
        g_c[f * 3 + 0] = make_float4(0.0f, 0.0f, -1.0f, 0.0f);
        g_c[f * 3 + 1] = make_float4(0.0f, 0.0f, 0.0f, 0.0f);
        g_c[f * 3 + 2] = make_float4(0.0f, 0.0f, 0.0f, 0.0f);
        g_bb[f] = make_float4(CUDART_INF_F, -CUDART_INF_F,
                              CUDART_INF_F, -CUDART_INF_F);   // never passes cull
        return;
    }

    float inv = 1.0f / area;          // fp32 reciprocal, same as reference
    float dy21 = y2 - y1, dx21 = x2 - x1;
    float dy02 = y0 - y2, dx02 = x0 - x2;
    float dy10 = y1 - y0, dx10 = x1 - x0;

    float gx0 = -dy21 * inv;
    float gy0 =  dx21 * inv;
    float k0  = cross_acc(dy21, x1, dx21, y1) * inv;
    float gx1 = -dy02 * inv;
    float gy1 =  dx02 * inv;
    float k1  = cross_acc(dy02, x2, dx02, y2) * inv;
    float gx2 = -dy10 * inv;
    float gy2 =  dx10 * inv;
    float k2  = cross_acc(dy10, x0, dx10, y0) * inv;

    float zx = dot3_acc(gx0, v0z, gx1, v1z, gx2, v2z);
    float zy = dot3_acc(gy0, v0z, gy1, v1z, gy2, v2z);
    float zk = dot3_acc(k0,  v0z, k1,  v1z, k2,  v2z);

    g_c[f * 3 + 0] = make_float4(gx0, gy0, k0, gx1);
    g_c[f * 3 + 1] = make_float4(gy1, k1, gx2, gy2);
    g_c[f * 3 + 2] = make_float4(k2, zx, zy, zk);

    float m = 2e-6f;
    g_bb[f] = make_float4(fminf(x0, fminf(x1, x2)) - m,
                          fmaxf(x0, fmaxf(x1, x2)) + m,
                          fminf(y0, fminf(y1, y2)) - m,
                          fmaxf(y0, fmaxf(y1, y2)) + m);
}

__global__ __launch_bounds__(BLOCK)
void raster_split_kernel(float* __restrict__ out, int F, int flen,
                         unsigned tailb, int niter) {
    __shared__ float4 sc[FLEN * 3];
    __shared__ float4 sbb[FLEN];
    __shared__ int    slist[WPB][FLEN];
    __shared__ unsigned sd;

    const unsigned NB = gridDim.x * gridDim.y;

    int s    = blockIdx.y;
    int fbeg = s * flen;
    int n    = F - fbeg;
    if (n > flen) n = flen;
    if (n < 0) n = 0;

    // stage this split's face data (global -> shared)
    for (int j = threadIdx.x; j < n * 3; j += BLOCK) sc[j]  = g_c[fbeg * 3 + j];
    for (int j = threadIdx.x; j < n;     j += BLOCK) sbb[j] = g_bb[fbeg + j];
    __syncthreads();

    int wid  = threadIdx.x >> 5;
    int lane = threadIdx.x & 31;
    // scatter: the 4 warps of a block take screen-distant tiles (load balance)
    int t    = wid * NBLKX + blockIdx.x;

    if (t < NTILES) {
        int tr = t / NTC;
        int tc = t - tr * NTC;
        int r0 = tr * TROWS;
        int r1 = min(r0 + TROWS - 1, H_OUT - 1);
        int c0 = tc * TCOLS;

        int  row   = r0 + lane;
        bool rowok = (row < H_OUT);
        float py   = pix_y(rowok ? row : (H_OUT - 1));

        // warp-uniform tile bounds (px decreases with c, py increases with r_out)
        float pyl = pix_y(r0);
        float pyh = pix_y(r1);
        float pxh = pix_x(c0);
        float pxl = pix_x(c0 + TCOLS - 1);

        // cull -> compacted ascending face list (per warp)
        int nlist = 0;
        for (int g = 0; g < n; g += 32) {
            int f = g + lane;
            bool pass = false;
            if (f < n) {
                float4 bb = sbb[f];
                pass = (bb.y >= pxl) & (bb.x <= pxh) & (bb.w >= pyl) & (bb.z <= pyh);
            }
            unsigned m = __ballot_sync(0xffffffffu, pass);
            if (pass) slist[wid][nlist + __popc(m & ((1u << lane) - 1u))] = f;
            nlist += __popc(m);
        }

        float px[TCOLS], z[TCOLS];
        int fb[TCOLS];
        #pragma unroll
        for (int k = 0; k < TCOLS; k++) {
            px[k] = pix_x(c0 + k);
            z[k]  = CUDART_INF_F;
            fb[k] = -1;
        }

        for (int j = 0; j < nlist; j++) {
            int f = slist[wid][j];
            float4 A = sc[f * 3 + 0];
            float4 B = sc[f * 3 + 1];
            float4 C = sc[f * 3 + 2];

            // per-lane (py) terms, shared across the 8 columns
            float t0 = fmaf(A.y, py, A.z);   // gy0*py + k0
            float t1 = fmaf(B.x, py, B.y);   // gy1*py + k1
            float t2 = fmaf(B.w, py, C.x);   // gy2*py + k2
            float tz = fmaf(C.z, py, C.w);   // zy*py + zk
            int   gf = fbeg + f;

            #pragma unroll
            for (int k = 0; k < TCOLS; k++) {
                float b0 = fmaf(A.x, px[k], t0);
                float b1 = fmaf(A.w, px[k], t1);
                float b2 = fmaf(B.z, px[k], t2);
                float zp = fmaf(C.y, px[k], tz);
                float mm = fminf(fminf(b0, b1), b2);
                float zc = (mm >= 0.0f) ? zp : CUDART_INF_F;
                if (zc < z[k]) { z[k] = zc; fb[k] = gf; }
            }
        }

        if (rowok) {
            int pbase = row * W_OUT + c0;
            #pragma unroll
            for (int k = 0; k < TCOLS; k++) {
                if (fb[k] >= 0) {
                    // inverted key: max over key == min z, tie -> min face index
                    unsigned long long key =
                        ((unsigned long long)(0xFFFFFFFFu - __float_as_uint(z[k])) << 32) |
                        (unsigned long long)(0xFFFFFFFFu - (unsigned)fb[k]);
                    atomicMax(&g_pk[pbase + k], key);
                }
            }
        }
    }

    // ---- arrival ticket; last `tailb` arrivals run the finalize tail ----
    __syncthreads();
    if (threadIdx.x == 0) {
        __threadfence();
        sd = atomicAdd(&g_ctr, 1u);
    }
    __syncthreads();
    unsigned d = sd;
    if (d < NB - tailb) return;    // early blocks exit; counter still reaches NB

    if (threadIdx.x == 0) {
        while (atomicAdd(&g_ctr, 0u) < NB) { __nanosleep(64); }
        __threadfence();
    }
    __syncthreads();

    // deterministic partition by ARRIVAL index (not block id)
    int sl_ = (int)(d - (NB - tailb));
    for (int i = 0; i < niter; i++) {
        int p = (sl_ * niter + i) * BLOCK + threadIdx.x;
        if (p >= NPIX) break;

        unsigned long long key = g_pk[p];
        g_pk[p] = 0ull;   // restore pristine state for the next graph replay

        int fbv = -1;
        float bb0 = -1.0f, bb1 = -1.0f, bb2 = -1.0f;

        if (key != 0ull) {
            fbv = (int)(0xFFFFFFFFu - (unsigned)(key & 0xFFFFFFFFull));
            float4 A = __ldg(&g_c[fbv * 3 + 0]);
            float4 B = __ldg(&g_c[fbv * 3 + 1]);
            float k2 = __ldg(&g_c[fbv * 3 + 2]).x;

            int row = p / W_OUT;
            int c   = p - row * W_OUT;
            float py = pix_y(row);
            float px = pix_x(c);

            // identical op order to the raster loop -> identical values
            float t0 = fmaf(A.y, py, A.z);
            float t1 = fmaf(B.x, py, B.y);
            float t2 = fmaf(B.w, py, k2);
            bb0 = fmaf(A.x, px, t0);
            bb1 = fmaf(A.w, px, t1);
            bb2 = fmaf(B.z, px, t2);
        }

        out[p] = (float)fbv;
        float* bary = out + NPIX + 3 * p;
        bary[0] = bb0;
        bary[1] = bb1;
        bary[2] = bb2;
    }

    // ---- reset protocol: last tail block restores the counters ----
    __syncthreads();
    if (threadIdx.x == 0) {
        __threadfence();
        unsigned e = atomicAdd(&g_ctr2, 1u);
        if (e == tailb - 1u) {
            atomicExch(&g_ctr, 0u);
            atomicExch(&g_ctr2, 0u);
        }
    }
}

extern "C" void kernel_launch(void* const* d_in, const int* in_sizes, int n_in,
                              void* d_out, int out_size) {
    const float* verts = (const float*)d_in[0];
    const int*   faces = (const int*)d_in[1];
    int F = in_sizes[1] / 3;
    if (F > MAXF) F = MAXF;

    int flen = FLEN;
    int nsplit = (F + FLEN - 1) / FLEN;
    if (nsplit < 1) nsplit = 1;

    unsigned NB = (unsigned)(NBLKX * nsplit);
    unsigned tailb = 64u;
    if (tailb > NB) tailb = NB;
    int niter = (NPIX + (int)tailb * BLOCK - 1) / ((int)tailb * BLOCK);

    face_setup_kernel<<<(F + 127) / 128, 128>>>(verts, faces, F);
    raster_split_kernel<<<dim3(NBLKX, nsplit), BLOCK>>>(
        (float*)d_out, F, flen, tailb, niter);
}

// round 13
// speedup vs baseline: 1.4110x; 1.0229x over previous
#include <cuda_runtime.h>
#include <cuda_bf16.h>
#include <math_constants.h>

#define H_OUT  135
#define W_OUT  240
#define NPIX   (H_OUT * W_OUT)   // 32400
#define EPS_A  1e-8f
#define Z_CLIP 0.01f

#define MAXF   4096
#define FLEN   128               // faces per split == BLOCK (1 face/thread in fold)

// Warp tile: 32 rows (lane) x 8 cols (k)
#define TROWS 32
#define TCOLS 8
#define NTR   ((H_OUT + TROWS - 1) / TROWS)   // 5
#define NTC   (W_OUT / TCOLS)                 // 30
#define NTILES (NTR * NTC)                    // 150
#define WPB   4
#define NBLKX ((NTILES + WPB - 1) / WPB)      // 38
#define BLOCK (32 * WPB)                      // 128

// Per-face folded coefficients, 3 x float4 (published for the tail phase):
//  C0 = (gx0, gy0, k0, gx1)
//  C1 = (gy1, k1, gx2, gy2)
//  C2 = (k2,  zx,  zy,  zk)
// b_i = gx_i*px + gy_i*py + k_i ;  zp = zx*px + zy*py + zk
__device__ float4 g_c[MAXF * 3];
// packed ((0xFFFFFFFF - z_bits) << 32) | (0xFFFFFFFF - face); 0 == empty.
// Zero-initialized at module load; tail phase resets to 0 every call.
__device__ unsigned long long g_pk[NPIX];
// arrival ticket + tail-completion counter; reset by the last tail block.
__device__ volatile unsigned g_ctr = 0;
__device__ unsigned g_ctr2 = 0;

__device__ __forceinline__ void project_v(float vx, float vy, float vz,
                                          float& xn, float& yn) {
    float xs = 1000.0f * (-vx) / vz + 960.0f;
    float ys = 1000.0f * vy    / vz + 540.0f;
    xn = -(2.0f * xs - 1920.0f) / 1080.0f;
    yn = -(2.0f * ys - 1080.0f) / 1080.0f;
}

__device__ __forceinline__ float pix_x(int c) {
    return -(2.0f * (float)c + 1.0f - (float)W_OUT) / 135.0f;
}
__device__ __forceinline__ float pix_y(int r_out) {
    int h = H_OUT - 1 - r_out;   // undo the [::-1] row flip
    return -(2.0f * (float)h + 1.0f - (float)H_OUT) / 135.0f;
}

// a*b - c*d with two-prod compensation (~0.5 ulp)
__device__ __forceinline__ float cross_acc(float a, float b, float c, float d) {
    float p1 = a * b;
    float e1 = fmaf(a, b, -p1);
    float p2 = c * d;
    float e2 = fmaf(c, d, -p2);
    return (p1 - p2) + (e1 - e2);
}

// a0*b0 + a1*b1 + a2*b2 with two-prod + two-sum compensation
__device__ __forceinline__ float dot3_acc(float a0, float b0,
                                          float a1, float b1,
                                          float a2, float b2) {
    float p0 = a0 * b0, e0 = fmaf(a0, b0, -p0);
    float p1 = a1 * b1, e1 = fmaf(a1, b1, -p1);
    float p2 = a2 * b2, e2 = fmaf(a2, b2, -p2);
    float s1 = p0 + p1;
    float v1 = s1 - p0;
    float t1 = (p0 - (s1 - v1)) + (p1 - v1);
    float s2 = s1 + p2;
    float v2 = s2 - s1;
    float t2 = (s1 - (s2 - v2)) + (p2 - v2);
    return s2 + (t1 + t2 + e0 + e1 + e2);
}

__global__ __launch_bounds__(BLOCK)
void raster_all_kernel(const float* __restrict__ verts,
                       const int*   __restrict__ faces,
                       float* __restrict__ out,
                       int F, unsigned tailb, int niter) {
    __shared__ float4 sc[FLEN * 3];
    __shared__ float4 sbb[FLEN];
    __shared__ int    slist[WPB][FLEN];
    __shared__ unsigned sd;

    const unsigned NB = gridDim.x * gridDim.y;

    int s    = blockIdx.y;
    int fbeg = s * FLEN;
    int n    = F - fbeg;
    if (n > FLEN) n = FLEN;
    if (n < 0) n = 0;

    // ---- phase 1: in-block fold, one face per thread, fp32 compensated ----
    int fl = threadIdx.x;
    if (fl < n) {
        int f = fbeg + fl;
        int i0 = faces[3 * f + 0];
        int i1 = faces[3 * f + 1];
        int i2 = faces[3 * f + 2];

        float v0z = verts[3 * i0 + 2];
        float v1z = verts[3 * i1 + 2];
        float v2z = verts[3 * i2 + 2];

        float x0, y0, x1, y1, x2, y2;
        project_v(verts[3 * i0], verts[3 * i0 + 1], v0z, x0, y0);
        project_v(verts[3 * i1], verts[3 * i1 + 1], v1z, x1, y1);
        project_v(verts[3 * i2], verts[3 * i2 + 1], v2z, x2, y2);

        float area = (x1 - x0) * (y2 - y0) - (y1 - y0) * (x2 - x0);
        bool ok = (fabsf(area) > EPS_A) &&
                  (v0z > Z_CLIP) && (v1z > Z_CLIP) && (v2z > Z_CLIP);

        float4 C0, C1, C2, BB;
        if (ok) {
            float inv = 1.0f / area;          // fp32 reciprocal, same as reference
            float dy21 = y2 - y1, dx21 = x2 - x1;
            float dy02 = y0 - y2, dx02 = x0 - x2;
            float dy10 = y1 - y0, dx10 = x1 - x0;

            float gx0 = -dy21 * inv;
            float gy0 =  dx21 * inv;
            float k0  = cross_acc(dy21, x1, dx21, y1) * inv;
            float gx1 = -dy02 * inv;
            float gy1 =  dx02 * inv;
            float k1  = cross_acc(dy02, x2, dx02, y2) * inv;
            float gx2 = -dy10 * inv;
            float gy2 =  dx10 * inv;
            float k2  = cross_acc(dy10, x0, dx10, y0) * inv;

            float zx = dot3_acc(gx0, v0z, gx1, v1z, gx2, v2z);
            float zy = dot3_acc(gy0, v0z, gy1, v1z, gy2, v2z);
            float zk = dot3_acc(k0,  v0z, k1,  v1z, k2,  v2z);

            C0 = make_float4(gx0, gy0, k0, gx1);
            C1 = make_float4(gy1, k1, gx2, gy2);
            C2 = make_float4(k2, zx, zy, zk);
            float m = 2e-6f;
            BB = make_float4(fminf(x0, fminf(x1, x2)) - m,
                             fmaxf(x0, fmaxf(x1, x2)) + m,
                             fminf(y0, fminf(y1, y2)) - m,
                             fmaxf(y0, fmaxf(y1, y2)) + m);
        } else {
            C0 = make_float4(0.0f, 0.0f, -1.0f, 0.0f);
            C1 = make_float4(0.0f, 0.0f, 0.0f, 0.0f);
            C2 = make_float4(0.0f, 0.0f, 0.0f, 0.0f);
            BB = make_float4(CUDART_INF_F, -CUDART_INF_F,
                             CUDART_INF_F, -CUDART_INF_F);   // never passes cull
        }

        sc[fl * 3 + 0] = C0;
        sc[fl * 3 + 1] = C1;
        sc[fl * 3 + 2] = C2;
        sbb[fl] = BB;

        if (blockIdx.x == 0) {            // one block per split publishes for the tail
            g_c[f * 3 + 0] = C0;
            g_c[f * 3 + 1] = C1;
            g_c[f * 3 + 2] = C2;
        }
    }
    __syncthreads();

    // ---- phase 2: raster ----
    int wid  = threadIdx.x >> 5;
    int lane = threadIdx.x & 31;
    // scatter: the 4 warps of a block take screen-distant tiles (load balance)
    int t    = wid * NBLKX + blockIdx.x;

    if (t < NTILES) {
        int tr = t / NTC;
        int tc = t - tr * NTC;
        int r0 = tr * TROWS;
        int r1 = min(r0 + TROWS - 1, H_OUT - 1);
        int c0 = tc * TCOLS;

        int  row   = r0 + lane;
        bool rowok = (row < H_OUT);
        float py   = pix_y(rowok ? row : (H_OUT - 1));

        // warp-uniform tile bounds (px decreases with c, py increases with r_out)
        float pyl = pix_y(r0);
        float pyh = pix_y(r1);
        float pxh = pix_x(c0);
        float pxl = pix_x(c0 + TCOLS - 1);

        // cull -> compacted ascending face list (per warp)
        int nlist = 0;
        for (int g = 0; g < n; g += 32) {
            int f = g + lane;
            bool pass = false;
            if (f < n) {
                float4 bb = sbb[f];
                pass = (bb.y >= pxl) & (bb.x <= pxh) & (bb.w >= pyl) & (bb.z <= pyh);
            }
            unsigned m = __ballot_sync(0xffffffffu, pass);
            if (pass) slist[wid][nlist + __popc(m & ((1u << lane) - 1u))] = f;
            nlist += __popc(m);
        }

        float px[TCOLS], z[TCOLS];
        int fb[TCOLS];
        #pragma unroll
        for (int k = 0; k < TCOLS; k++) {
            px[k] = pix_x(c0 + k);
            z[k]  = CUDART_INF_F;
            fb[k] = -1;
        }

        for (int j = 0; j < nlist; j++) {
            int f = slist[wid][j];
            float4 A = sc[f * 3 + 0];
            float4 B = sc[f * 3 + 1];
            float4 C = sc[f * 3 + 2];

            // per-lane (py) terms, shared across the 8 columns
            float t0 = fmaf(A.y, py, A.z);   // gy0*py + k0
            float t1 = fmaf(B.x, py, B.y);   // gy1*py + k1
            float t2 = fmaf(B.w, py, C.x);   // gy2*py + k2
            float tz = fmaf(C.z, py, C.w);   // zy*py + zk
            int   gf = fbeg + f;

            #pragma unroll
            for (int k = 0; k < TCOLS; k++) {
                float b0 = fmaf(A.x, px[k], t0);
                float b1 = fmaf(A.w, px[k], t1);
                float b2 = fmaf(B.z, px[k], t2);
                float zp = fmaf(C.y, px[k], tz);
                float mm = fminf(fminf(b0, b1), b2);
                float zc = (mm >= 0.0f) ? zp : CUDART_INF_F;
                if (zc < z[k]) { z[k] = zc; fb[k] = gf; }
            }
        }

        if (rowok) {
            int pbase = row * W_OUT + c0;
            #pragma unroll
            for (int k = 0; k < TCOLS; k++) {
                if (fb[k] >= 0) {
                    // inverted key: max over key == min z, tie -> min face index
                    unsigned long long key =
                        ((unsigned long long)(0xFFFFFFFFu - __float_as_uint(z[k])) << 32) |
                        (unsigned long long)(0xFFFFFFFFu - (unsigned)fb[k]);
                    atomicMax(&g_pk[pbase + k], key);
                }
            }
        }
    }

    // ---- phase 3: arrival ticket; last `tailb` arrivals finalize ----
    __syncthreads();
    if (threadIdx.x == 0) {
        __threadfence();
        sd = atomicAdd((unsigned*)&g_ctr, 1u);
    }
    __syncthreads();
    unsigned d = sd;
    if (d < NB - tailb) return;    // early blocks exit; counter still reaches NB

    if (threadIdx.x == 0) {
        while (g_ctr < NB) { __nanosleep(64); }
        __threadfence();
    }
    __syncthreads();

    // deterministic partition by ARRIVAL slot (each slot = fixed pixel range)
    int sl_ = (int)(d - (NB - tailb));
    for (int i = 0; i < niter; i++) {
        int p = (sl_ * niter + i) * BLOCK + threadIdx.x;
        if (p >= NPIX) break;

        unsigned long long key = g_pk[p];
        g_pk[p] = 0ull;   // restore pristine state for the next graph replay

        int fbv = -1;
        float bb0 = -1.0f, bb1 = -1.0f, bb2 = -1.0f;

        if (key != 0ull) {
            fbv = (int)(0xFFFFFFFFu - (unsigned)(key & 0xFFFFFFFFull));
            float4 A = __ldg(&g_c[fbv * 3 + 0]);
            float4 B = __ldg(&g_c[fbv * 3 + 1]);
            float k2 = __ldg(&g_c[fbv * 3 + 2]).x;

            int row = p / W_OUT;
            int c   = p - row * W_OUT;
            float py = pix_y(row);
            float px = pix_x(c);

            // identical op order to the raster loop -> identical values
            float t0 = fmaf(A.y, py, A.z);
            float t1 = fmaf(B.x, py, B.y);
            float t2 = fmaf(B.w, py, k2);
            bb0 = fmaf(A.x, px, t0);
            bb1 = fmaf(A.w, px, t1);
            bb2 = fmaf(B.z, px, t2);
        }

        out[p] = (float)fbv;
        float* bary = out + NPIX + 3 * p;
        bary[0] = bb0;
        bary[1] = bb1;
        bary[2] = bb2;
    }

    // ---- reset protocol: last tail block restores the counters ----
    __syncthreads();
    if (threadIdx.x == 0) {
        __threadfence();
        unsigned e = atomicAdd(&g_ctr2, 1u);
        if (e == tailb - 1u) {
            g_ctr  = 0u;
            atomicExch(&g_ctr2, 0u);
        }
    }
}

extern "C" void kernel_launch(void* const* d_in, const int* in_sizes, int n_in,
                              void* d_out, int out_size) {
    const float* verts = (const float*)d_in[0];
    const int*   faces = (const int*)d_in[1];
    int F = in_sizes[1] / 3;
    if (F > MAXF) F = MAXF;

    int nsplit = (F + FLEN - 1) / FLEN;
    if (nsplit < 1) nsplit = 1;

    unsigned NB = (unsigned)(NBLKX * nsplit);
    unsigned tailb = 254u;                       // niter == 1 for NPIX=32400
    if (tailb > NB) tailb = NB;
    int niter = (NPIX + (int)tailb * BLOCK - 1) / ((int)tailb * BLOCK);

    raster_all_kernel<<<dim3(NBLKX, nsplit), BLOCK>>>(
        verts, faces, (float*)d_out, F, tailb, niter);
}

// round 14
// speedup vs baseline: 1.5067x; 1.0678x over previous
#include <cuda_runtime.h>
#include <cuda_bf16.h>
#include <math_constants.h>

#define H_OUT  135
#define W_OUT  240
#define NPIX   (H_OUT * W_OUT)   // 32400
#define EPS_A  1e-8f
#define Z_CLIP 0.01f

#define MAXF   4096
#define NSPLIT 16
#define FLEN_MAX 256             // cap; actual flen = 128 for F=2048

// Warp tile: 32 rows (lane) x 8 cols (k)
#define TROWS 32
#define TCOLS 8
#define NTR   ((H_OUT + TROWS - 1) / TROWS)   // 5
#define NTC   (W_OUT / TCOLS)                 // 30
#define NTILES (NTR * NTC)                    // 150
#define WPB   4
#define NBLKX ((NTILES + WPB - 1) / WPB)      // 38
#define BLOCK (32 * WPB)                      // 128

// Per-face folded coefficients, 3 x float4 (global copy, for finalize):
//  C0 = (gx0, gy0, k0, gx1)
//  C1 = (gy1, k1, gx2, gy2)
//  C2 = (k2,  zx,  zy,  zk)
// b_i = gx_i*px + gy_i*py + k_i ;  zp = zx*px + zy*py + zk
__device__ float4 g_c[MAXF * 3];
// packed ((0xFFFFFFFF - z_bits) << 32) | (0xFFFFFFFF - face); 0 == empty.
// Zero-initialized at module load; finalize resets to 0 every call,
// so every graph replay starts from identical state.
__device__ unsigned long long g_pk[NPIX];

__device__ __forceinline__ void project_v(float vx, float vy, float vz,
                                          float& xn, float& yn) {
    float xs = 1000.0f * (-vx) / vz + 960.0f;
    float ys = 1000.0f * vy    / vz + 540.0f;
    xn = -(2.0f * xs - 1920.0f) / 1080.0f;
    yn = -(2.0f * ys - 1080.0f) / 1080.0f;
}

__device__ __forceinline__ float pix_x(int c) {
    return -(2.0f * (float)c + 1.0f - (float)W_OUT) / 135.0f;
}
__device__ __forceinline__ float pix_y(int r_out) {
    int h = H_OUT - 1 - r_out;   // undo the [::-1] row flip
    return -(2.0f * (float)h + 1.0f - (float)H_OUT) / 135.0f;
}

// a*b - c*d with two-prod compensation (~0.5 ulp)
__device__ __forceinline__ float cross_acc(float a, float b, float c, float d) {
    float p1 = a * b;
    float e1 = fmaf(a, b, -p1);
    float p2 = c * d;
    float e2 = fmaf(c, d, -p2);
    return (p1 - p2) + (e1 - e2);
}

// a0*b0 + a1*b1 + a2*b2 with two-prod + two-sum compensation
__device__ __forceinline__ float dot3_acc(float a0, float b0,
                                          float a1, float b1,
                                          float a2, float b2) {
    float p0 = a0 * b0, e0 = fmaf(a0, b0, -p0);
    float p1 = a1 * b1, e1 = fmaf(a1, b1, -p1);
    float p2 = a2 * b2, e2 = fmaf(a2, b2, -p2);
    float s1 = p0 + p1;
    float v1 = s1 - p0;
    float t1 = (p0 - (s1 - v1)) + (p1 - v1);
    float s2 = s1 + p2;
    float v2 = s2 - s1;
    float t2 = (s1 - (s2 - v2)) + (p2 - v2);
    return s2 + (t1 + t2 + e0 + e1 + e2);
}

__global__ __launch_bounds__(BLOCK)
void raster_fused_kernel(const float* __restrict__ verts,
                         const int*   __restrict__ faces,
                         int F, int flen) {
    __shared__ float4 sc[FLEN_MAX * 3];
    __shared__ float4 sbb[FLEN_MAX];
    __shared__ int    slist[WPB][FLEN_MAX];

    int s    = blockIdx.y;
    int fbeg = s * flen;
    int n    = F - fbeg;
    if (n > flen) n = flen;
    if (n < 0) n = 0;

    // ---- in-block face setup: one face per thread (flen <= BLOCK), fp32 ----
    int fl = threadIdx.x;                  // local face index
    if (fl < n) {
        int f = fbeg + fl;
        int i0 = faces[3 * f + 0];
        int i1 = faces[3 * f + 1];
        int i2 = faces[3 * f + 2];

        float v0z = verts[3 * i0 + 2];
        float v1z = verts[3 * i1 + 2];
        float v2z = verts[3 * i2 + 2];

        float x0, y0, x1, y1, x2, y2;
        project_v(verts[3 * i0], verts[3 * i0 + 1], v0z, x0, y0);
        project_v(verts[3 * i1], verts[3 * i1 + 1], v1z, x1, y1);
        project_v(verts[3 * i2], verts[3 * i2 + 1], v2z, x2, y2);

        float area = (x1 - x0) * (y2 - y0) - (y1 - y0) * (x2 - x0);
        bool ok = (fabsf(area) > EPS_A) &&
                  (v0z > Z_CLIP) && (v1z > Z_CLIP) && (v2z > Z_CLIP);

        float4 C0, C1, C2, BB;
        if (ok) {
            float inv = 1.0f / area;          // fp32 reciprocal, same as reference
            float dy21 = y2 - y1, dx21 = x2 - x1;
            float dy02 = y0 - y2, dx02 = x0 - x2;
            float dy10 = y1 - y0, dx10 = x1 - x0;

            float gx0 = -dy21 * inv;
            float gy0 =  dx21 * inv;
            float k0  = cross_acc(dy21, x1, dx21, y1) * inv;
            float gx1 = -dy02 * inv;
            float gy1 =  dx02 * inv;
            float k1  = cross_acc(dy02, x2, dx02, y2) * inv;
            float gx2 = -dy10 * inv;
            float gy2 =  dx10 * inv;
            float k2  = cross_acc(dy10, x0, dx10, y0) * inv;

            float zx = dot3_acc(gx0, v0z, gx1, v1z, gx2, v2z);
            float zy = dot3_acc(gy0, v0z, gy1, v1z, gy2, v2z);
            float zk = dot3_acc(k0,  v0z, k1,  v1z, k2,  v2z);

            C0 = make_float4(gx0, gy0, k0, gx1);
            C1 = make_float4(gy1, k1, gx2, gy2);
            C2 = make_float4(k2, zx, zy, zk);
            float m = 2e-6f;
            BB = make_float4(fminf(x0, fminf(x1, x2)) - m,
                             fmaxf(x0, fmaxf(x1, x2)) + m,
                             fminf(y0, fminf(y1, y2)) - m,
                             fmaxf(y0, fmaxf(y1, y2)) + m);
        } else {
            C0 = make_float4(0.0f, 0.0f, -1.0f, 0.0f);
            C1 = make_float4(0.0f, 0.0f, 0.0f, 0.0f);
            C2 = make_float4(0.0f, 0.0f, 0.0f, 0.0f);
            BB = make_float4(CUDART_INF_F, -CUDART_INF_F,
                             CUDART_INF_F, -CUDART_INF_F);   // never passes cull
        }

        sc[fl * 3 + 0] = C0;
        sc[fl * 3 + 1] = C1;
        sc[fl * 3 + 2] = C2;
        sbb[fl] = BB;

        if (blockIdx.x == 0) {            // one block per split publishes for finalize
            g_c[f * 3 + 0] = C0;
            g_c[f * 3 + 1] = C1;
            g_c[f * 3 + 2] = C2;
        }
    }
    __syncthreads();

    // ---- raster ----
    int wid  = threadIdx.x >> 5;
    int lane = threadIdx.x & 31;
    // scatter: the 4 warps of a block take screen-distant tiles (load balance)
    int t    = wid * NBLKX + blockIdx.x;
    if (t >= NTILES) return;

    int tr = t / NTC;
    int tc = t - tr * NTC;
    int r0 = tr * TROWS;
    int r1 = min(r0 + TROWS - 1, H_OUT - 1);
    int c0 = tc * TCOLS;

    int  row   = r0 + lane;
    bool rowok = (row < H_OUT);
    float py   = pix_y(rowok ? row : (H_OUT - 1));

    // warp-uniform tile bounds (px decreases with c, py increases with r_out)
    float pyl = pix_y(r0);
    float pyh = pix_y(r1);
    float pxh = pix_x(c0);
    float pxl = pix_x(c0 + TCOLS - 1);

    // cull -> compacted ascending face list (per warp)
    int nlist = 0;
    for (int g = 0; g < n; g += 32) {
        int f = g + lane;
        bool pass = false;
        if (f < n) {
            float4 bb = sbb[f];
            pass = (bb.y >= pxl) & (bb.x <= pxh) & (bb.w >= pyl) & (bb.z <= pyh);
        }
        unsigned m = __ballot_sync(0xffffffffu, pass);
        if (pass) slist[wid][nlist + __popc(m & ((1u << lane) - 1u))] = f;
        nlist += __popc(m);
    }

    float px[TCOLS], z[TCOLS];
    int fb[TCOLS];
    #pragma unroll
    for (int k = 0; k < TCOLS; k++) {
        px[k] = pix_x(c0 + k);
        z[k]  = CUDART_INF_F;
        fb[k] = -1;
    }

    for (int j = 0; j < nlist; j++) {
        int f = slist[wid][j];
        float4 A = sc[f * 3 + 0];
        float4 B = sc[f * 3 + 1];
        float4 C = sc[f * 3 + 2];

        // per-lane (py) terms, shared across the 8 columns
        float t0 = fmaf(A.y, py, A.z);   // gy0*py + k0
        float t1 = fmaf(B.x, py, B.y);   // gy1*py + k1
        float t2 = fmaf(B.w, py, C.x);   // gy2*py + k2
        float tz = fmaf(C.z, py, C.w);   // zy*py + zk
        int   gf = fbeg + f;

        #pragma unroll
        for (int k = 0; k < TCOLS; k++) {
            float b0 = fmaf(A.x, px[k], t0);
            float b1 = fmaf(A.w, px[k], t1);
            float b2 = fmaf(B.z, px[k], t2);
            float zp = fmaf(C.y, px[k], tz);
            float mm = fminf(fminf(b0, b1), b2);
            float zc = (mm >= 0.0f) ? zp : CUDART_INF_F;
            if (zc < z[k]) { z[k] = zc; fb[k] = gf; }
        }
    }

    if (rowok) {
        int pbase = row * W_OUT + c0;
        #pragma unroll
        for (int k = 0; k < TCOLS; k++) {
            if (fb[k] >= 0) {
                // inverted key: max over key == min z, tie -> min face index
                unsigned long long key =
                    ((unsigned long long)(0xFFFFFFFFu - __float_as_uint(z[k])) << 32) |
                    (unsigned long long)(0xFFFFFFFFu - (unsigned)fb[k]);
                atomicMax(&g_pk[pbase + k], key);
            }
        }
    }
}

__global__ __launch_bounds__(128)
void finalize_kernel(float* __restrict__ out) {
    int p = blockIdx.x * 128 + threadIdx.x;
    if (p >= NPIX) return;

    unsigned long long key = g_pk[p];
    g_pk[p] = 0ull;   // restore pristine state for the next graph replay

    int fbv = -1;
    float bb0 = -1.0f, bb1 = -1.0f, bb2 = -1.0f;

    if (key != 0ull) {
        fbv = (int)(0xFFFFFFFFu - (unsigned)(key & 0xFFFFFFFFull));
        float4 A = g_c[fbv * 3 + 0];
        float4 B = g_c[fbv * 3 + 1];
        float k2 = g_c[fbv * 3 + 2].x;

        int row = p / W_OUT;
        int c   = p - row * W_OUT;
        float py = pix_y(row);
        float px = pix_x(c);

        // identical op order to the raster loop -> identical values
        float t0 = fmaf(A.y, py, A.z);
        float t1 = fmaf(B.x, py, B.y);
        float t2 = fmaf(B.w, py, k2);
        bb0 = fmaf(A.x, px, t0);
        bb1 = fmaf(A.w, px, t1);
        bb2 = fmaf(B.z, px, t2);
    }

    out[p] = (float)fbv;
    float* bary = out + NPIX + 3 * p;
    bary[0] = bb0;
    bary[1] = bb1;
    bary[2] = bb2;
}

extern "C" void kernel_launch(void* const* d_in, const int* in_sizes, int n_in,
                              void* d_out, int out_size) {
    const float* verts = (const float*)d_in[0];
    const int*   faces = (const int*)d_in[1];
    int F = in_sizes[1] / 3;
    if (F > MAXF) F = MAXF;

    int flen = (F + NSPLIT - 1) / NSPLIT;
    if (flen > BLOCK) flen = BLOCK;            // 1-face-per-thread invariant
    if (flen < 1) flen = 1;
    int nsplit = (F + flen - 1) / flen;
    if (nsplit < 1) nsplit = 1;

    raster_fused_kernel<<<dim3(NBLKX, nsplit), BLOCK>>>(verts, faces, F, flen);
    finalize_kernel<<<(NPIX + 127) / 128, 128>>>((float*)d_out);
}

// round 15
// speedup vs baseline: 1.9234x; 1.2766x over previous
#include <cuda_runtime.h>
#include <cuda_bf16.h>
#include <math_constants.h>

#define H_OUT  135
#define W_OUT  240
#define NPIX   (H_OUT * W_OUT)   // 32400
#define EPS_A  1e-8f
#define Z_CLIP 0.01f

#define MAXF   4096
#define NSPLIT 32
#define FLEN_MAX 64              // faces per split (F=2048 -> flen=64)

// Warp tile: 32 rows (lane) x 8 cols (k)
#define TROWS 32
#define TCOLS 8
#define NTR   ((H_OUT + TROWS - 1) / TROWS)   // 5
#define NTC   (W_OUT / TCOLS)                 // 30
#define NTILES (NTR * NTC)                    // 150
#define WPB   4
#define NBLKX ((NTILES + WPB - 1) / WPB)      // 38
#define BLOCK (32 * WPB)                      // 128

// Per-face folded coefficients, 3 x float4 (global copy, for finalize):
//  C0 = (gx0, gy0, k0, gx1)
//  C1 = (gy1, k1, gx2, gy2)
//  C2 = (k2,  zx,  zy,  zk)
// b_i = gx_i*px + gy_i*py + k_i ;  zp = zx*px + zy*py + zk
__device__ float4 g_c[MAXF * 3];
// packed ((0xFFFFFFFF - z_bits) << 32) | (0xFFFFFFFF - face); 0 == empty.
// Zero-initialized at module load; finalize resets to 0 every call,
// so every graph replay starts from identical state.
__device__ unsigned long long g_pk[NPIX];

__device__ __forceinline__ void project_v(float vx, float vy, float vz,
                                          float& xn, float& yn) {
    float xs = 1000.0f * (-vx) / vz + 960.0f;
    float ys = 1000.0f * vy    / vz + 540.0f;
    xn = -(2.0f * xs - 1920.0f) / 1080.0f;
    yn = -(2.0f * ys - 1080.0f) / 1080.0f;
}

__device__ __forceinline__ float pix_x(int c) {
    return -(2.0f * (float)c + 1.0f - (float)W_OUT) / 135.0f;
}
__device__ __forceinline__ float pix_y(int r_out) {
    int h = H_OUT - 1 - r_out;   // undo the [::-1] row flip
    return -(2.0f * (float)h + 1.0f - (float)H_OUT) / 135.0f;
}

// a*b - c*d with two-prod compensation (~0.5 ulp)
__device__ __forceinline__ float cross_acc(float a, float b, float c, float d) {
    float p1 = a * b;
    float e1 = fmaf(a, b, -p1);
    float p2 = c * d;
    float e2 = fmaf(c, d, -p2);
    return (p1 - p2) + (e1 - e2);
}

// a0*b0 + a1*b1 + a2*b2 with two-prod + two-sum compensation
__device__ __forceinline__ float dot3_acc(float a0, float b0,
                                          float a1, float b1,
                                          float a2, float b2) {
    float p0 = a0 * b0, e0 = fmaf(a0, b0, -p0);
    float p1 = a1 * b1, e1 = fmaf(a1, b1, -p1);
    float p2 = a2 * b2, e2 = fmaf(a2, b2, -p2);
    float s1 = p0 + p1;
    float v1 = s1 - p0;
    float t1 = (p0 - (s1 - v1)) + (p1 - v1);
    float s2 = s1 + p2;
    float v2 = s2 - s1;
    float t2 = (s1 - (s2 - v2)) + (p2 - v2);
    return s2 + (t1 + t2 + e0 + e1 + e2);
}

__global__ __launch_bounds__(BLOCK)
void raster_fused_kernel(const float* __restrict__ verts,
                         const int*   __restrict__ faces,
                         int F, int flen) {
    __shared__ float4 sc[FLEN_MAX * 3];
    __shared__ float4 sbb[FLEN_MAX];
    __shared__ int    slist[WPB][FLEN_MAX];

    int s    = blockIdx.y;
    int fbeg = s * flen;
    int n    = F - fbeg;
    if (n > flen) n = flen;
    if (n < 0) n = 0;

    // ---- in-block face setup: one face per thread (flen <= BLOCK), fp32 ----
    int fl = threadIdx.x;                  // local face index
    if (fl < n) {
        int f = fbeg + fl;
        int i0 = faces[3 * f + 0];
        int i1 = faces[3 * f + 1];
        int i2 = faces[3 * f + 2];

        float v0z = verts[3 * i0 + 2];
        float v1z = verts[3 * i1 + 2];
        float v2z = verts[3 * i2 + 2];

        float x0, y0, x1, y1, x2, y2;
        project_v(verts[3 * i0], verts[3 * i0 + 1], v0z, x0, y0);
        project_v(verts[3 * i1], verts[3 * i1 + 1], v1z, x1, y1);
        project_v(verts[3 * i2], verts[3 * i2 + 1], v2z, x2, y2);

        float area = (x1 - x0) * (y2 - y0) - (y1 - y0) * (x2 - x0);
        bool ok = (fabsf(area) > EPS_A) &&
                  (v0z > Z_CLIP) && (v1z > Z_CLIP) && (v2z > Z_CLIP);

        float4 C0, C1, C2, BB;
        if (ok) {
            float inv = 1.0f / area;          // fp32 reciprocal, same as reference
            float dy21 = y2 - y1, dx21 = x2 - x1;
            float dy02 = y0 - y2, dx02 = x0 - x2;
            float dy10 = y1 - y0, dx10 = x1 - x0;

            float gx0 = -dy21 * inv;
            float gy0 =  dx21 * inv;
            float k0  = cross_acc(dy21, x1, dx21, y1) * inv;
            float gx1 = -dy02 * inv;
            float gy1 =  dx02 * inv;
            float k1  = cross_acc(dy02, x2, dx02, y2) * inv;
            float gx2 = -dy10 * inv;
            float gy2 =  dx10 * inv;
            float k2  = cross_acc(dy10, x0, dx10, y0) * inv;

            float zx = dot3_acc(gx0, v0z, gx1, v1z, gx2, v2z);
            float zy = dot3_acc(gy0, v0z, gy1, v1z, gy2, v2z);
            float zk = dot3_acc(k0,  v0z, k1,  v1z, k2,  v2z);

            C0 = make_float4(gx0, gy0, k0, gx1);
            C1 = make_float4(gy1, k1, gx2, gy2);
            C2 = make_float4(k2, zx, zy, zk);
            float m = 2e-6f;
            BB = make_float4(fminf(x0, fminf(x1, x2)) - m,
                             fmaxf(x0, fmaxf(x1, x2)) + m,
                             fminf(y0, fminf(y1, y2)) - m,
                             fmaxf(y0, fmaxf(y1, y2)) + m);
        } else {
            C0 = make_float4(0.0f, 0.0f, -1.0f, 0.0f);
            C1 = make_float4(0.0f, 0.0f, 0.0f, 0.0f);
            C2 = make_float4(0.0f, 0.0f, 0.0f, 0.0f);
            BB = make_float4(CUDART_INF_F, -CUDART_INF_F,
                             CUDART_INF_F, -CUDART_INF_F);   // never passes cull
        }

        sc[fl * 3 + 0] = C0;
        sc[fl * 3 + 1] = C1;
        sc[fl * 3 + 2] = C2;
        sbb[fl] = BB;

        if (blockIdx.x == 0) {            // one block per split publishes for finalize
            g_c[f * 3 + 0] = C0;
            g_c[f * 3 + 1] = C1;
            g_c[f * 3 + 2] = C2;
        }
    }
    __syncthreads();

    // ---- raster ----
    int wid  = threadIdx.x >> 5;
    int lane = threadIdx.x & 31;
    // block-adjacent tiles (R6 champion config)
    int t    = blockIdx.x * WPB + wid;
    if (t >= NTILES) return;

    int tr = t / NTC;
    int tc = t - tr * NTC;
    int r0 = tr * TROWS;
    int r1 = min(r0 + TROWS - 1, H_OUT - 1);
    int c0 = tc * TCOLS;

    int  row   = r0 + lane;
    bool rowok = (row < H_OUT);
    float py   = pix_y(rowok ? row : (H_OUT - 1));

    // warp-uniform tile bounds (px decreases with c, py increases with r_out)
    float pyl = pix_y(r0);
    float pyh = pix_y(r1);
    float pxh = pix_x(c0);
    float pxl = pix_x(c0 + TCOLS - 1);

    // cull -> compacted ascending face list (per warp)
    int nlist = 0;
    for (int g = 0; g < n; g += 32) {
        int f = g + lane;
        bool pass = false;
        if (f < n) {
            float4 bb = sbb[f];
            pass = (bb.y >= pxl) & (bb.x <= pxh) & (bb.w >= pyl) & (bb.z <= pyh);
        }
        unsigned m = __ballot_sync(0xffffffffu, pass);
        if (pass) slist[wid][nlist + __popc(m & ((1u << lane) - 1u))] = f;
        nlist += __popc(m);
    }

    float px[TCOLS], z[TCOLS];
    int fb[TCOLS];
    #pragma unroll
    for (int k = 0; k < TCOLS; k++) {
        px[k] = pix_x(c0 + k);
        z[k]  = CUDART_INF_F;
        fb[k] = -1;
    }

    for (int j = 0; j < nlist; j++) {
        int f = slist[wid][j];
        float4 A = sc[f * 3 + 0];
        float4 B = sc[f * 3 + 1];
        float4 C = sc[f * 3 + 2];

        // per-lane (py) terms, shared across the 8 columns
        float t0 = fmaf(A.y, py, A.z);   // gy0*py + k0
        float t1 = fmaf(B.x, py, B.y);   // gy1*py + k1
        float t2 = fmaf(B.w, py, C.x);   // gy2*py + k2
        float tz = fmaf(C.z, py, C.w);   // zy*py + zk
        int   gf = fbeg + f;

        #pragma unroll
        for (int k = 0; k < TCOLS; k++) {
            float b0 = fmaf(A.x, px[k], t0);
            float b1 = fmaf(A.w, px[k], t1);
            float b2 = fmaf(B.z, px[k], t2);
            float zp = fmaf(C.y, px[k], tz);
            float mm = fminf(fminf(b0, b1), b2);
            float zc = (mm >= 0.0f) ? zp : CUDART_INF_F;
            if (zc < z[k]) { z[k] = zc; fb[k] = gf; }
        }
    }

    if (rowok) {
        int pbase = row * W_OUT + c0;
        #pragma unroll
        for (int k = 0; k < TCOLS; k++) {
            if (fb[k] >= 0) {
                // inverted key: max over key == min z, tie -> min face index
                unsigned long long key =
                    ((unsigned long long)(0xFFFFFFFFu - __float_as_uint(z[k])) << 32) |
                    (unsigned long long)(0xFFFFFFFFu - (unsigned)fb[k]);
                atomicMax(&g_pk[pbase + k], key);
            }
        }
    }
}

__global__ __launch_bounds__(128)
void finalize_kernel(float* __restrict__ out) {
    int p = blockIdx.x * 128 + threadIdx.x;
    if (p >= NPIX) return;

    unsigned long long key = g_pk[p];
    g_pk[p] = 0ull;   // restore pristine state for the next graph replay

    int fbv = -1;
    float bb0 = -1.0f, bb1 = -1.0f, bb2 = -1.0f;

    if (key != 0ull) {
        fbv = (int)(0xFFFFFFFFu - (unsigned)(key & 0xFFFFFFFFull));
        float4 A = g_c[fbv * 3 + 0];
        float4 B = g_c[fbv * 3 + 1];
        float k2 = g_c[fbv * 3 + 2].x;

        int row = p / W_OUT;
        int c   = p - row * W_OUT;
        float py = pix_y(row);
        float px = pix_x(c);

        // identical op order to the raster loop -> identical values
        float t0 = fmaf(A.y, py, A.z);
        float t1 = fmaf(B.x, py, B.y);
        float t2 = fmaf(B.w, py, k2);
        bb0 = fmaf(A.x, px, t0);
        bb1 = fmaf(A.w, px, t1);
        bb2 = fmaf(B.z, px, t2);
    }

    out[p] = (float)fbv;
    float* bary = out + NPIX + 3 * p;
    bary[0] = bb0;
    bary[1] = bb1;
    bary[2] = bb2;
}

extern "C" void kernel_launch(void* const* d_in, const int* in_sizes, int n_in,
                              void* d_out, int out_size) {
    const float* verts = (const float*)d_in[0];
    const int*   faces = (const int*)d_in[1];
    int F = in_sizes[1] / 3;
    if (F > MAXF) F = MAXF;

    int flen = (F + NSPLIT - 1) / NSPLIT;
    if (flen > FLEN_MAX) flen = FLEN_MAX;      // 1-face-per-thread invariant
    if (flen < 1) flen = 1;
    int nsplit = (F + flen - 1) / flen;
    if (nsplit < 1) nsplit = 1;

    raster_fused_kernel<<<dim3(NBLKX, nsplit), BLOCK>>>(verts, faces, F, flen);
    finalize_kernel<<<(NPIX + 127) / 128, 128>>>((float*)d_out);
}

// round 16
// speedup vs baseline: 2.0209x; 1.0507x over previous
#include <cuda_runtime.h>
#include <cuda_bf16.h>
#include <math_constants.h>

#define H_OUT  135
#define W_OUT  240
#define NPIX   (H_OUT * W_OUT)   // 32400
#define EPS_A  1e-8f
#define Z_CLIP 0.01f

#define MAXF   4096
#define NSPLIT 64
#define FLEN_MAX 32              // faces per split (F=2048 -> flen=32)

// Warp tile: 32 rows (lane) x 8 cols (k)
#define TROWS 32
#define TCOLS 8
#define NTR   ((H_OUT + TROWS - 1) / TROWS)   // 5
#define NTC   (W_OUT / TCOLS)                 // 30
#define NTILES (NTR * NTC)                    // 150
#define WPB   4
#define NBLKX ((NTILES + WPB - 1) / WPB)      // 38
#define BLOCK (32 * WPB)                      // 128

// Per-face folded coefficients, 3 x float4 (global copy, for finalize):
//  C0 = (gx0, gy0, k0, gx1)
//  C1 = (gy1, k1, gx2, gy2)
//  C2 = (k2,  zx,  zy,  zk)
// b_i = gx_i*px + gy_i*py + k_i ;  zp = zx*px + zy*py + zk
__device__ float4 g_c[MAXF * 3];
// packed ((0xFFFFFFFF - z_bits) << 32) | (0xFFFFFFFF - face); 0 == empty.
// Zero-initialized at module load; finalize resets to 0 every call,
// so every graph replay starts from identical state.
__device__ unsigned long long g_pk[NPIX];

__device__ __forceinline__ void project_v(float vx, float vy, float vz,
                                          float& xn, float& yn) {
    float xs = 1000.0f * (-vx) / vz + 960.0f;
    float ys = 1000.0f * vy    / vz + 540.0f;
    xn = -(2.0f * xs - 1920.0f) / 1080.0f;
    yn = -(2.0f * ys - 1080.0f) / 1080.0f;
}

__device__ __forceinline__ float pix_x(int c) {
    return -(2.0f * (float)c + 1.0f - (float)W_OUT) / 135.0f;
}
__device__ __forceinline__ float pix_y(int r_out) {
    int h = H_OUT - 1 - r_out;   // undo the [::-1] row flip
    return -(2.0f * (float)h + 1.0f - (float)H_OUT) / 135.0f;
}

// a*b - c*d with two-prod compensation (~0.5 ulp)
__device__ __forceinline__ float cross_acc(float a, float b, float c, float d) {
    float p1 = a * b;
    float e1 = fmaf(a, b, -p1);
    float p2 = c * d;
    float e2 = fmaf(c, d, -p2);
    return (p1 - p2) + (e1 - e2);
}

// a0*b0 + a1*b1 + a2*b2 with two-prod + two-sum compensation
__device__ __forceinline__ float dot3_acc(float a0, float b0,
                                          float a1, float b1,
                                          float a2, float b2) {
    float p0 = a0 * b0, e0 = fmaf(a0, b0, -p0);
    float p1 = a1 * b1, e1 = fmaf(a1, b1, -p1);
    float p2 = a2 * b2, e2 = fmaf(a2, b2, -p2);
    float s1 = p0 + p1;
    float v1 = s1 - p0;
    float t1 = (p0 - (s1 - v1)) + (p1 - v1);
    float s2 = s1 + p2;
    float v2 = s2 - s1;
    float t2 = (s1 - (s2 - v2)) + (p2 - v2);
    return s2 + (t1 + t2 + e0 + e1 + e2);
}

__global__ __launch_bounds__(BLOCK)
void raster_fused_kernel(const float* __restrict__ verts,
                         const int*   __restrict__ faces,
                         int F, int flen) {
    __shared__ float4 sc[FLEN_MAX * 3];
    __shared__ float4 sbb[FLEN_MAX];
    __shared__ int    slist[WPB][FLEN_MAX];

    int s    = blockIdx.y;
    int fbeg = s * flen;
    int n    = F - fbeg;
    if (n > flen) n = flen;
    if (n < 0) n = 0;

    // ---- in-block face setup: one face per thread (flen <= BLOCK), fp32 ----
    int fl = threadIdx.x;                  // local face index
    if (fl < n) {
        int f = fbeg + fl;
        int i0 = faces[3 * f + 0];
        int i1 = faces[3 * f + 1];
        int i2 = faces[3 * f + 2];

        float v0z = verts[3 * i0 + 2];
        float v1z = verts[3 * i1 + 2];
        float v2z = verts[3 * i2 + 2];

        float x0, y0, x1, y1, x2, y2;
        project_v(verts[3 * i0], verts[3 * i0 + 1], v0z, x0, y0);
        project_v(verts[3 * i1], verts[3 * i1 + 1], v1z, x1, y1);
        project_v(verts[3 * i2], verts[3 * i2 + 1], v2z, x2, y2);

        float area = (x1 - x0) * (y2 - y0) - (y1 - y0) * (x2 - x0);
        bool ok = (fabsf(area) > EPS_A) &&
                  (v0z > Z_CLIP) && (v1z > Z_CLIP) && (v2z > Z_CLIP);

        float4 C0, C1, C2, BB;
        if (ok) {
            float inv = 1.0f / area;          // fp32 reciprocal, same as reference
            float dy21 = y2 - y1, dx21 = x2 - x1;
            float dy02 = y0 - y2, dx02 = x0 - x2;
            float dy10 = y1 - y0, dx10 = x1 - x0;

            float gx0 = -dy21 * inv;
            float gy0 =  dx21 * inv;
            float k0  = cross_acc(dy21, x1, dx21, y1) * inv;
            float gx1 = -dy02 * inv;
            float gy1 =  dx02 * inv;
            float k1  = cross_acc(dy02, x2, dx02, y2) * inv;
            float gx2 = -dy10 * inv;
            float gy2 =  dx10 * inv;
            float k2  = cross_acc(dy10, x0, dx10, y0) * inv;

            float zx = dot3_acc(gx0, v0z, gx1, v1z, gx2, v2z);
            float zy = dot3_acc(gy0, v0z, gy1, v1z, gy2, v2z);
            float zk = dot3_acc(k0,  v0z, k1,  v1z, k2,  v2z);

            C0 = make_float4(gx0, gy0, k0, gx1);
            C1 = make_float4(gy1, k1, gx2, gy2);
            C2 = make_float4(k2, zx, zy, zk);
            float m = 2e-6f;
            BB = make_float4(fminf(x0, fminf(x1, x2)) - m,
                             fmaxf(x0, fmaxf(x1, x2)) + m,
                             fminf(y0, fminf(y1, y2)) - m,
                             fmaxf(y0, fmaxf(y1, y2)) + m);
        } else {
            C0 = make_float4(0.0f, 0.0f, -1.0f, 0.0f);
            C1 = make_float4(0.0f, 0.0f, 0.0f, 0.0f);
            C2 = make_float4(0.0f, 0.0f, 0.0f, 0.0f);
            BB = make_float4(CUDART_INF_F, -CUDART_INF_F,
                             CUDART_INF_F, -CUDART_INF_F);   // never passes cull
        }

        sc[fl * 3 + 0] = C0;
        sc[fl * 3 + 1] = C1;
        sc[fl * 3 + 2] = C2;
        sbb[fl] = BB;

        if (blockIdx.x == 0) {            // one block per split publishes for finalize
            g_c[f * 3 + 0] = C0;
            g_c[f * 3 + 1] = C1;
            g_c[f * 3 + 2] = C2;
        }
    }
    __syncthreads();

    // ---- raster ----
    int wid  = threadIdx.x >> 5;
    int lane = threadIdx.x & 31;
    // block-adjacent tiles (R6 champion config)
    int t    = blockIdx.x * WPB + wid;
    if (t >= NTILES) return;

    int tr = t / NTC;
    int tc = t - tr * NTC;
    int r0 = tr * TROWS;
    int r1 = min(r0 + TROWS - 1, H_OUT - 1);
    int c0 = tc * TCOLS;

    int  row   = r0 + lane;
    bool rowok = (row < H_OUT);
    float py   = pix_y(rowok ? row : (H_OUT - 1));

    // warp-uniform tile bounds (px decreases with c, py increases with r_out)
    float pyl = pix_y(r0);
    float pyh = pix_y(r1);
    float pxh = pix_x(c0);
    float pxl = pix_x(c0 + TCOLS - 1);

    // cull -> compacted ascending face list (per warp)
    int nlist = 0;
    for (int g = 0; g < n; g += 32) {
        int f = g + lane;
        bool pass = false;
        if (f < n) {
            float4 bb = sbb[f];
            pass = (bb.y >= pxl) & (bb.x <= pxh) & (bb.w >= pyl) & (bb.z <= pyh);
        }
        unsigned m = __ballot_sync(0xffffffffu, pass);
        if (pass) slist[wid][nlist + __popc(m & ((1u << lane) - 1u))] = f;
        nlist += __popc(m);
    }

    float px[TCOLS], z[TCOLS];
    int fb[TCOLS];
    #pragma unroll
    for (int k = 0; k < TCOLS; k++) {
        px[k] = pix_x(c0 + k);
        z[k]  = CUDART_INF_F;
        fb[k] = -1;
    }

    for (int j = 0; j < nlist; j++) {
        int f = slist[wid][j];
        float4 A = sc[f * 3 + 0];
        float4 B = sc[f * 3 + 1];
        float4 C = sc[f * 3 + 2];

        // per-lane (py) terms, shared across the 8 columns
        float t0 = fmaf(A.y, py, A.z);   // gy0*py + k0
        float t1 = fmaf(B.x, py, B.y);   // gy1*py + k1
        float t2 = fmaf(B.w, py, C.x);   // gy2*py + k2
        float tz = fmaf(C.z, py, C.w);   // zy*py + zk
        int   gf = fbeg + f;

        #pragma unroll
        for (int k = 0; k < TCOLS; k++) {
            float b0 = fmaf(A.x, px[k], t0);
            float b1 = fmaf(A.w, px[k], t1);
            float b2 = fmaf(B.z, px[k], t2);
            float zp = fmaf(C.y, px[k], tz);
            float mm = fminf(fminf(b0, b1), b2);
            float zc = (mm >= 0.0f) ? zp : CUDART_INF_F;
            if (zc < z[k]) { z[k] = zc; fb[k] = gf; }
        }
    }

    if (rowok) {
        int pbase = row * W_OUT + c0;
        #pragma unroll
        for (int k = 0; k < TCOLS; k++) {
            if (fb[k] >= 0) {
                // inverted key: max over key == min z, tie -> min face index
                unsigned long long key =
                    ((unsigned long long)(0xFFFFFFFFu - __float_as_uint(z[k])) << 32) |
                    (unsigned long long)(0xFFFFFFFFu - (unsigned)fb[k]);
                atomicMax(&g_pk[pbase + k], key);
            }
        }
    }
}

__global__ __launch_bounds__(256)
void finalize_kernel(float* __restrict__ out) {
    int p = blockIdx.x * 256 + threadIdx.x;
    if (p >= NPIX) return;

    unsigned long long key = g_pk[p];
    g_pk[p] = 0ull;   // restore pristine state for the next graph replay

    int fbv = -1;
    float bb0 = -1.0f, bb1 = -1.0f, bb2 = -1.0f;

    if (key != 0ull) {
        fbv = (int)(0xFFFFFFFFu - (unsigned)(key & 0xFFFFFFFFull));
        float4 A = g_c[fbv * 3 + 0];
        float4 B = g_c[fbv * 3 + 1];
        float k2 = g_c[fbv * 3 + 2].x;

        int row = p / W_OUT;
        int c   = p - row * W_OUT;
        float py = pix_y(row);
        float px = pix_x(c);

        // identical op order to the raster loop -> identical values
        float t0 = fmaf(A.y, py, A.z);
        float t1 = fmaf(B.x, py, B.y);
        float t2 = fmaf(B.w, py, k2);
        bb0 = fmaf(A.x, px, t0);
        bb1 = fmaf(A.w, px, t1);
        bb2 = fmaf(B.z, px, t2);
    }

    out[p] = (float)fbv;
    float* bary = out + NPIX + 3 * p;
    bary[0] = bb0;
    bary[1] = bb1;
    bary[2] = bb2;
}

extern "C" void kernel_launch(void* const* d_in, const int* in_sizes, int n_in,
                              void* d_out, int out_size) {
    const float* verts = (const float*)d_in[0];
    const int*   faces = (const int*)d_in[1];
    int F = in_sizes[1] / 3;
    if (F > MAXF) F = MAXF;

    int flen = (F + NSPLIT - 1) / NSPLIT;
    if (flen > FLEN_MAX) flen = FLEN_MAX;      // 1-face-per-thread invariant
    if (flen < 1) flen = 1;
    int nsplit = (F + flen - 1) / flen;
    if (nsplit < 1) nsplit = 1;

    raster_fused_kernel<<<dim3(NBLKX, nsplit), BLOCK>>>(verts, faces, F, flen);
    finalize_kernel<<<(NPIX + 255) / 256, 256>>>((float*)d_out);
}